// round 3
// baseline (speedup 1.0000x reference)
#include <cuda_runtime.h>
#include <math.h>

// Problem constants
#define BSZ   64
#define SLEN  4096
#define EMB   266
#define HID   512
#define NH    128
#define ROWS  (BSZ * NH)   // 8192
#define URows (NH + BSZ)   // 192: emb rows then z rows

// GEMM tiling
#define BM 128
#define BN 128
#define BK 16
#define TM 8
#define TN 8

// Static device scratch (no allocations allowed)
__device__ float g_UV[URows * HID];      // [0:128)=emb@w_in, [128:192)=z@w_in
__device__ float g_H0[ROWS * HID];       // activation ping
__device__ float g_H1[ROWS * HID];       // activation pong
__device__ float g_coef[ROWS * 2];       // [sin_c, cos_c] per (b, h)

__device__ __forceinline__ float silu_f(float v) {
    return v * (1.0f / (1.0f + __expf(-v)));
}

// ---------------------------------------------------------------------------
// Input projection, exploiting A0 = z[b] + emb[h]:
//   UV[r] = (r<128 ? emb[r] : z[r-128]) @ w_in        (192 x 266 x 512)
// One block per row; row cached in smem; thread c does cols c and c+256.
// ---------------------------------------------------------------------------
__global__ void __launch_bounds__(256)
in_gemm(const float* __restrict__ z, const float* __restrict__ emb,
        const float* __restrict__ w_in) {
    __shared__ float row[EMB];
    const int r = blockIdx.x;
    const float* src = (r < NH) ? (emb + (size_t)r * EMB)
                                : (z + (size_t)(r - NH) * EMB);
    for (int k = threadIdx.x; k < EMB; k += 256) row[k] = src[k];
    __syncthreads();

    const int c = threadIdx.x;
    float a0 = 0.f, a1 = 0.f;
    #pragma unroll 2
    for (int k = 0; k < EMB; k++) {
        float rv = row[k];
        a0 = fmaf(rv, w_in[(size_t)k * HID + c],        a0);
        a1 = fmaf(rv, w_in[(size_t)k * HID + c + 256],  a1);
    }
    g_UV[(size_t)r * HID + c]       = a0;
    g_UV[(size_t)r * HID + c + 256] = a1;
}

// ---------------------------------------------------------------------------
// Combine: H0[b,h,:] = silu(UV[h] + UV[128+b] + b_in)   (float4 vectorized)
// ---------------------------------------------------------------------------
__global__ void __launch_bounds__(256)
combine_kernel(const float* __restrict__ b_in) {
    int idx4 = blockIdx.x * blockDim.x + threadIdx.x;  // over ROWS*HID/4
    int c4 = idx4 & (HID / 4 - 1);                     // 0..127
    int r  = idx4 >> 7;                                // row 0..8191
    int b = r >> 7, h = r & 127;

    float4 u = *reinterpret_cast<const float4*>(&g_UV[(size_t)h * HID + c4 * 4]);
    float4 v = *reinterpret_cast<const float4*>(&g_UV[(size_t)(NH + b) * HID + c4 * 4]);
    float4 bb = *reinterpret_cast<const float4*>(&b_in[c4 * 4]);
    float4 o;
    o.x = silu_f(u.x + v.x + bb.x);
    o.y = silu_f(u.y + v.y + bb.y);
    o.z = silu_f(u.z + v.z + bb.z);
    o.w = silu_f(u.w + v.w + bb.w);
    *reinterpret_cast<float4*>(&g_H0[(size_t)r * HID + c4 * 4]) = o;
}

// ---------------------------------------------------------------------------
// SGEMM with fused bias + silu:  C[8192, 512] = silu(A[M,K] @ B[K,512] + bias)
// 128x128 tile, 8x8 per thread, 256 threads. Double-buffered shared memory:
// one __syncthreads per K-tile; global prefetch + smem commit of tile k+1
// overlap the FMA block of tile k.
// ---------------------------------------------------------------------------
__global__ void __launch_bounds__(256, 2)
gemm_silu(const float* __restrict__ A, const float* __restrict__ B,
          const float* __restrict__ bias, float* __restrict__ C, int K) {
    __shared__ float As[2][BK][BM + 4];   // padded: conflict-free transpose store
    __shared__ float Bs[2][BK][BN];

    const int tid = threadIdx.x;
    const int bx = blockIdx.x;     // N tile (0..3)
    const int by = blockIdx.y;     // M tile (0..63)

    const float* Ablk = A + (size_t)by * BM * K;
    const float* Bblk = B + bx * BN;

    const int tx = tid & 15;
    const int ty = tid >> 4;

    // A-tile: 128 rows x 16 cols, 2 float4 per thread
    const int a_row = tid >> 2;          // 0..63
    const int a_col = (tid & 3) * 4;     // 0,4,8,12
    // B-tile: 16 rows x 128 cols, 2 float4 per thread
    const int b_row = tid >> 5;          // 0..7
    const int b_col = (tid & 31) * 4;    // 0..124

    float acc[TM][TN] = {};

    // Prologue: load tile 0 and commit to buffer 0
    {
        float4 a0 = *reinterpret_cast<const float4*>(Ablk + (size_t)a_row        * K + a_col);
        float4 a1 = *reinterpret_cast<const float4*>(Ablk + (size_t)(a_row + 64) * K + a_col);
        float4 b0 = *reinterpret_cast<const float4*>(Bblk + (size_t)b_row       * HID + b_col);
        float4 b1 = *reinterpret_cast<const float4*>(Bblk + (size_t)(b_row + 8) * HID + b_col);
        As[0][a_col + 0][a_row] = a0.x;
        As[0][a_col + 1][a_row] = a0.y;
        As[0][a_col + 2][a_row] = a0.z;
        As[0][a_col + 3][a_row] = a0.w;
        As[0][a_col + 0][a_row + 64] = a1.x;
        As[0][a_col + 1][a_row + 64] = a1.y;
        As[0][a_col + 2][a_row + 64] = a1.z;
        As[0][a_col + 3][a_row + 64] = a1.w;
        *reinterpret_cast<float4*>(&Bs[0][b_row][b_col])     = b0;
        *reinterpret_cast<float4*>(&Bs[0][b_row + 8][b_col]) = b1;
    }

    int buf = 0;
    for (int k0 = 0; k0 < K; k0 += BK) {
        __syncthreads();      // buffer `buf` visible to all warps

        // Prefetch next K-tile into registers (long-latency loads issue first)
        const int kn = k0 + BK;
        float4 aS0, aS1, bS0, bS1;
        const bool more = (kn < K);
        if (more) {
            aS0 = *reinterpret_cast<const float4*>(Ablk + (size_t)a_row        * K + kn + a_col);
            aS1 = *reinterpret_cast<const float4*>(Ablk + (size_t)(a_row + 64) * K + kn + a_col);
            bS0 = *reinterpret_cast<const float4*>(Bblk + (size_t)(kn + b_row)     * HID + b_col);
            bS1 = *reinterpret_cast<const float4*>(Bblk + (size_t)(kn + b_row + 8) * HID + b_col);
        }

        // Compute on buffer `buf`
        #pragma unroll
        for (int kk = 0; kk < BK; kk++) {
            float aR[TM], bR[TN];
            #pragma unroll
            for (int i = 0; i < TM; i++) aR[i] = As[buf][kk][ty * TM + i];
            #pragma unroll
            for (int j = 0; j < TN; j++) bR[j] = Bs[buf][kk][tx * TN + j];
            #pragma unroll
            for (int i = 0; i < TM; i++)
                #pragma unroll
                for (int j = 0; j < TN; j++)
                    acc[i][j] = fmaf(aR[i], bR[j], acc[i][j]);
        }

        // Commit staged registers to the other buffer (no barrier needed:
        // next iteration's __syncthreads orders it before any read)
        if (more) {
            int nb = buf ^ 1;
            As[nb][a_col + 0][a_row] = aS0.x;
            As[nb][a_col + 1][a_row] = aS0.y;
            As[nb][a_col + 2][a_row] = aS0.z;
            As[nb][a_col + 3][a_row] = aS0.w;
            As[nb][a_col + 0][a_row + 64] = aS1.x;
            As[nb][a_col + 1][a_row + 64] = aS1.y;
            As[nb][a_col + 2][a_row + 64] = aS1.z;
            As[nb][a_col + 3][a_row + 64] = aS1.w;
            *reinterpret_cast<float4*>(&Bs[nb][b_row][b_col])     = bS0;
            *reinterpret_cast<float4*>(&Bs[nb][b_row + 8][b_col]) = bS1;
            buf = nb;
        }
    }

    // Epilogue: bias + silu, vectorized store
    const int crow = by * BM + ty * TM;
    const int ccol = bx * BN + tx * TN;
    float bv[TN];
    #pragma unroll
    for (int j = 0; j < TN; j++) bv[j] = bias[ccol + j];

    #pragma unroll
    for (int i = 0; i < TM; i++) {
        float4 v0, v1;
        v0.x = silu_f(acc[i][0] + bv[0]);
        v0.y = silu_f(acc[i][1] + bv[1]);
        v0.z = silu_f(acc[i][2] + bv[2]);
        v0.w = silu_f(acc[i][3] + bv[3]);
        v1.x = silu_f(acc[i][4] + bv[4]);
        v1.y = silu_f(acc[i][5] + bv[5]);
        v1.z = silu_f(acc[i][6] + bv[6]);
        v1.w = silu_f(acc[i][7] + bv[7]);
        float* cp = C + (size_t)(crow + i) * HID + ccol;
        *reinterpret_cast<float4*>(cp)     = v0;
        *reinterpret_cast<float4*>(cp + 4) = v1;
    }
}

// ---------------------------------------------------------------------------
// Output projection: coef[r, 0:2] = H[r, :] @ w_out + b_out (one warp per row)
// ---------------------------------------------------------------------------
__global__ void out_proj(const float* __restrict__ H,
                         const float* __restrict__ w_out,
                         const float* __restrict__ b_out) {
    int warp = (blockIdx.x * blockDim.x + threadIdx.x) >> 5;
    int lane = threadIdx.x & 31;
    if (warp >= ROWS) return;
    const float* h = H + (size_t)warp * HID;
    float a0 = 0.f, a1 = 0.f;
    #pragma unroll
    for (int k = lane; k < HID; k += 32) {
        float hv = h[k];
        float2 w = *reinterpret_cast<const float2*>(w_out + 2 * k);
        a0 = fmaf(hv, w.x, a0);
        a1 = fmaf(hv, w.y, a1);
    }
    #pragma unroll
    for (int o = 16; o; o >>= 1) {
        a0 += __shfl_xor_sync(0xffffffffu, a0, o);
        a1 += __shfl_xor_sync(0xffffffffu, a1, o);
    }
    if (lane == 0) {
        g_coef[2 * warp + 0] = a0 + b_out[0];   // sin coefficient
        g_coef[2 * warp + 1] = a1 + b_out[1];   // cos coefficient
    }
}

// ---------------------------------------------------------------------------
// Synthesis: FREQS = integers 1..128 -> one accurate sincos per point, then a
// 128-step angle-addition recurrence (4 FMA/harmonic). Drift ~1e-5 << 1e-3.
// ---------------------------------------------------------------------------
__global__ void __launch_bounds__(256)
synth_kernel(const float* __restrict__ target_x, float* __restrict__ out) {
    __shared__ float sc[NH], cc[NH];
    const int b = blockIdx.y;
    const int t = threadIdx.x;
    if (t < NH) {
        float2 v = *reinterpret_cast<const float2*>(&g_coef[(b * NH + t) * 2]);
        sc[t] = v.x;
        cc[t] = v.y;
    }
    __syncthreads();

    const int s = blockIdx.x * blockDim.x + t;
    float xv = target_x[b * SLEN + s];
    float theta = 6.283185307179586f * xv;
    float s1, c1;
    sincosf(theta, &s1, &c1);

    float ch = c1, sh = s1;            // h = 1 (freq 1)
    float acc = 0.f;
    #pragma unroll 8
    for (int h = 0; h < NH; h++) {
        acc = fmaf(ch, cc[h], acc);
        acc = fmaf(sh, sc[h], acc);
        float nc = fmaf(ch, c1, -sh * s1);
        float ns = fmaf(sh, c1,  ch * s1);
        ch = nc;
        sh = ns;
    }
    out[b * SLEN + s] = acc;
}

// ---------------------------------------------------------------------------
// Launch sequence
// ---------------------------------------------------------------------------
extern "C" void kernel_launch(void* const* d_in, const int* in_sizes, int n_in,
                              void* d_out, int out_size) {
    const float* target_x = (const float*)d_in[0];  // (64, 4096, 1)
    const float* z        = (const float*)d_in[1];  // (64, 266)
    // d_in[2] = x : unused by the reference
    const float* emb      = (const float*)d_in[3];  // (128, 266)
    const float* w_in     = (const float*)d_in[4];  // (266, 512)
    const float* b_in     = (const float*)d_in[5];  // (512,)
    const float* w_h      = (const float*)d_in[6];  // (3, 512, 512)
    const float* b_h      = (const float*)d_in[7];  // (3, 512)
    const float* w_out    = (const float*)d_in[8];  // (512, 2)
    const float* b_out    = (const float*)d_in[9];  // (2,)
    float* out = (float*)d_out;                     // (64, 4096)

    float *H0, *H1;
    cudaGetSymbolAddress((void**)&H0, g_H0);
    cudaGetSymbolAddress((void**)&H1, g_H1);

    // 1) input projection on the rank-structured layer-0 input
    in_gemm<<<URows, 256>>>(z, emb, w_in);

    // 2) combine + bias + silu -> H0
    combine_kernel<<<(ROWS * HID / 4) / 256, 256>>>(b_in);

    // 3) hidden layers: (8192 x 512) @ (512 x 512), silu fused
    dim3 gg(HID / BN, ROWS / BM);   // (4, 64)
    gemm_silu<<<gg, 256>>>(H0, w_h + 0 * HID * HID, b_h + 0 * HID, H1, HID);
    gemm_silu<<<gg, 256>>>(H1, w_h + 1 * HID * HID, b_h + 1 * HID, H0, HID);
    gemm_silu<<<gg, 256>>>(H0, w_h + 2 * HID * HID, b_h + 2 * HID, H1, HID);

    // 4) output projection -> coefficients
    out_proj<<<(ROWS * 32) / 256, 256>>>(H1, w_out, b_out);

    // 5) Fourier synthesis
    dim3 sg(SLEN / 256, BSZ);
    synth_kernel<<<sg, 256>>>(target_x, out);
}

// round 9
// speedup vs baseline: 1.8949x; 1.8949x over previous
#include <cuda_runtime.h>
#include <cuda_bf16.h>
#include <cstdint>
#include <math.h>

// Problem constants
#define BSZ   64
#define SLEN  4096
#define EMB   266
#define HID   512
#define NH    128
#define ROWS  (BSZ * NH)   // 8192
#define URows (NH + BSZ)   // 192

// mma.sync GEMM tiling
#define TILE_M 128
#define TILE_N 128
#define BK     32                 // K chunk per stage
#define NCHUNK (HID / BK)         // 16
#define LDT    40                 // smem row stride in bf16 (32 + 8 pad)
#define LDTB   (LDT * 2)          // 80 bytes
#define TILEB  (128 * LDTB)       // 10240 bytes per operand tile
#define SM_BIAS_BYTES 512
#define SM_TOTAL (SM_BIAS_BYTES + 8 * TILEB)   // 82432

// Static device scratch (no allocations allowed)
__device__ float g_UV[URows * HID];
__device__ float g_coef[ROWS * 2];
__device__ __nv_bfloat16 g_Ah[2][ROWS * HID];   // activation hi, ping/pong
__device__ __nv_bfloat16 g_Al[2][ROWS * HID];   // activation lo
__device__ __nv_bfloat16 g_Wh[3 * HID * HID];   // weights hi, [l][n][k]
__device__ __nv_bfloat16 g_Wl[3 * HID * HID];   // weights lo

__device__ __forceinline__ float silu_f(float v) {
    return v * (1.0f / (1.0f + __expf(-v)));
}

__device__ __forceinline__ uint32_t smem_u32(const void* p) {
    uint32_t a;
    asm("{ .reg .u64 t; cvta.to.shared.u64 t, %1; cvt.u32.u64 %0, t; }" : "=r"(a) : "l"(p));
    return a;
}

// ---------------- sm_80-class primitives (no 'a'-suffix features) ----------
#define CP_ASYNC16(dst, src) \
    asm volatile("cp.async.cg.shared.global [%0], [%1], 16;" :: "r"(dst), "l"(src))
#define CP_COMMIT() asm volatile("cp.async.commit_group;" ::: "memory")
#define CP_WAIT(n)  asm volatile("cp.async.wait_group %0;" :: "n"(n) : "memory")

#define LDSM4(r, addr)                                                         \
    asm volatile("ldmatrix.sync.aligned.m8n8.x4.shared.b16 {%0,%1,%2,%3}, [%4];" \
        : "=r"((r)[0]), "=r"((r)[1]), "=r"((r)[2]), "=r"((r)[3]) : "r"(addr))
#define LDSM2(r, addr)                                                         \
    asm volatile("ldmatrix.sync.aligned.m8n8.x2.shared.b16 {%0,%1}, [%2];"     \
        : "=r"((r)[0]), "=r"((r)[1]) : "r"(addr))

#define MMA_BF16(d, a, b)                                                      \
    asm volatile("mma.sync.aligned.m16n8k16.row.col.f32.bf16.bf16.f32 "        \
        "{%0,%1,%2,%3}, {%4,%5,%6,%7}, {%8,%9}, {%0,%1,%2,%3};"                \
        : "+f"((d)[0]), "+f"((d)[1]), "+f"((d)[2]), "+f"((d)[3])               \
        : "r"((a)[0]), "r"((a)[1]), "r"((a)[2]), "r"((a)[3]),                  \
          "r"((b)[0]), "r"((b)[1]))

// Stage one 128x32 bf16 tile (global row stride HID) into padded smem rows.
__device__ __forceinline__ void stage_in(uint32_t sbase,
                                         const __nv_bfloat16* __restrict__ g,
                                         int tid) {
    #pragma unroll
    for (int it = 0; it < 2; it++) {
        int idx = tid + it * 256;      // 0..511
        int row = idx >> 2;            // 0..127
        int seg = idx & 3;             // 16B segment within the 64B row chunk
        uint32_t dst = sbase + row * LDTB + seg * 16;
        const __nv_bfloat16* src = g + (size_t)row * HID + seg * 8;
        CP_ASYNC16(dst, src);
    }
}

// ---------------------------------------------------------------------------
// Tensor-core GEMM via mma.sync: C = silu(A @ B^T + bias), bf16x3 split,
// output re-split to hi/lo bf16. A: [8192,512] row-major, B: [512(N),512(K)].
// Grid (4, 64) = (nt, mt); 256 threads = 8 warps (2 M x 4 N), warp tile 64x32.
// ---------------------------------------------------------------------------
__global__ void __launch_bounds__(256)
gemm_mma(const __nv_bfloat16* __restrict__ Ah, const __nv_bfloat16* __restrict__ Al,
         const __nv_bfloat16* __restrict__ Bh, const __nv_bfloat16* __restrict__ Bl,
         const float* __restrict__ bias,
         __nv_bfloat16* __restrict__ Ch, __nv_bfloat16* __restrict__ Cl) {
    extern __shared__ char smem[];
    const uint32_t sb = smem_u32(smem);
    float* sBias = reinterpret_cast<float*>(smem);

    const int tid = threadIdx.x;
    const int lane = tid & 31;
    const int wid = tid >> 5;
    const int wm = wid & 1;        // warp row (2)
    const int wn = wid >> 1;       // warp col (4)
    const int nt = blockIdx.x, mt = blockIdx.y;

    if (tid < TILE_N) sBias[tid] = bias[nt * TILE_N + tid];

    const __nv_bfloat16* aH = Ah + (size_t)(mt * TILE_M) * HID;
    const __nv_bfloat16* aL = Al + (size_t)(mt * TILE_M) * HID;
    const __nv_bfloat16* bH = Bh + (size_t)(nt * TILE_N) * HID;
    const __nv_bfloat16* bL = Bl + (size_t)(nt * TILE_N) * HID;

    // tile offset: stage s (0/1), operand o (0=Ah 1=Al 2=Bh 3=Bl)
    #define TOFF(s, o) (SM_BIAS_BYTES + ((s) * 4 + (o)) * TILEB)

    // Prefetch stage 0
    stage_in(sb + TOFF(0, 0), aH, tid);
    stage_in(sb + TOFF(0, 1), aL, tid);
    stage_in(sb + TOFF(0, 2), bH, tid);
    stage_in(sb + TOFF(0, 3), bL, tid);
    CP_COMMIT();

    float acc[4][4][4] = {};

    // Per-lane ldmatrix addressing
    const int amat = lane >> 3;                       // 0..3
    const int arow = (lane & 7) + (amat & 1) * 8;     // row within 16
    const int akb  = (amat >> 1) * 16;                // 0 or 16 bytes (k half)
    const int bidx = lane & 15;
    const int brow = bidx & 7;                        // n-row within 8
    const int bkb  = (bidx >> 3) * 16;                // 0 or 16 bytes (k half)

    for (int c = 0; c < NCHUNK; c++) {
        const int cur = c & 1;
        if (c + 1 < NCHUNK) {
            const int k0 = (c + 1) * BK;
            const int nx = cur ^ 1;
            stage_in(sb + TOFF(nx, 0), aH + k0, tid);
            stage_in(sb + TOFF(nx, 1), aL + k0, tid);
            stage_in(sb + TOFF(nx, 2), bH + k0, tid);
            stage_in(sb + TOFF(nx, 3), bL + k0, tid);
            CP_COMMIT();
            CP_WAIT(1);
        } else {
            CP_WAIT(0);
        }
        __syncthreads();

        const uint32_t sAh = sb + TOFF(cur, 0);
        const uint32_t sAl = sb + TOFF(cur, 1);
        const uint32_t sBh = sb + TOFF(cur, 2);
        const uint32_t sBl = sb + TOFF(cur, 3);

        #pragma unroll
        for (int ks = 0; ks < 2; ks++) {
            uint32_t ah[4][4], al[4][4], bh2[4][2], bl2[4][2];
            const int kb = ks * 32;
            #pragma unroll
            for (int mi = 0; mi < 4; mi++) {
                uint32_t off = (uint32_t)((wm * 64 + mi * 16 + arow) * LDTB + kb + akb);
                LDSM4(ah[mi], sAh + off);
                LDSM4(al[mi], sAl + off);
            }
            #pragma unroll
            for (int nj = 0; nj < 4; nj++) {
                uint32_t off = (uint32_t)((wn * 32 + nj * 8 + brow) * LDTB + kb + bkb);
                LDSM2(bh2[nj], sBh + off);
                LDSM2(bl2[nj], sBl + off);
            }
            #pragma unroll
            for (int mi = 0; mi < 4; mi++)
                #pragma unroll
                for (int nj = 0; nj < 4; nj++) {
                    MMA_BF16(acc[mi][nj], ah[mi], bh2[nj]);   // hi*hi
                    MMA_BF16(acc[mi][nj], al[mi], bh2[nj]);   // lo*hi
                    MMA_BF16(acc[mi][nj], ah[mi], bl2[nj]);   // hi*lo
                }
        }
        __syncthreads();
    }

    // Epilogue: bias + silu, re-split to hi/lo bf16
    const int lm = lane >> 2, ln = lane & 3;
    #pragma unroll
    for (int mi = 0; mi < 4; mi++) {
        #pragma unroll
        for (int nj = 0; nj < 4; nj++) {
            const float* a = acc[mi][nj];
            const int row  = mt * TILE_M + wm * 64 + mi * 16 + lm;
            const int colL = wn * 32 + nj * 8 + ln * 2;
            const int col  = nt * TILE_N + colL;
            const float b0 = sBias[colL], b1 = sBias[colL + 1];
            #pragma unroll
            for (int half = 0; half < 2; half++) {
                const int r = row + half * 8;
                const float v0 = silu_f(a[half * 2 + 0] + b0);
                const float v1 = silu_f(a[half * 2 + 1] + b1);
                __nv_bfloat16 h0 = __float2bfloat16(v0);
                __nv_bfloat16 h1 = __float2bfloat16(v1);
                __nv_bfloat162 hp, lp;
                hp.x = h0; hp.y = h1;
                lp.x = __float2bfloat16(v0 - __bfloat162float(h0));
                lp.y = __float2bfloat16(v1 - __bfloat162float(h1));
                const size_t o = (size_t)r * HID + col;
                *reinterpret_cast<__nv_bfloat162*>(Ch + o) = hp;
                *reinterpret_cast<__nv_bfloat162*>(Cl + o) = lp;
            }
        }
    }
}

// ---------------------------------------------------------------------------
// Weight prep: g_W{h,l}[l][n][k] = split(w_h[l][k][n])  (transpose + bf16 split)
// ---------------------------------------------------------------------------
__global__ void wprep(const float* __restrict__ w_h) {
    int idx = blockIdx.x * blockDim.x + threadIdx.x;
    if (idx >= 3 * HID * HID) return;
    int l = idx >> 18;
    int rem = idx & (HID * HID - 1);
    int n = rem >> 9, k = rem & 511;
    float v = w_h[(size_t)l * HID * HID + (size_t)k * HID + n];
    __nv_bfloat16 h = __float2bfloat16(v);
    g_Wh[idx] = h;
    g_Wl[idx] = __float2bfloat16(v - __bfloat162float(h));
}

// ---------------------------------------------------------------------------
// Input projection (rank-structured layer 0): UV[r] = (emb|z)[r] @ w_in
// ---------------------------------------------------------------------------
__global__ void __launch_bounds__(256)
in_gemm(const float* __restrict__ z, const float* __restrict__ emb,
        const float* __restrict__ w_in) {
    __shared__ float row[EMB];
    const int r = blockIdx.x;
    const float* src = (r < NH) ? (emb + (size_t)r * EMB)
                                : (z + (size_t)(r - NH) * EMB);
    for (int k = threadIdx.x; k < EMB; k += 256) row[k] = src[k];
    __syncthreads();

    const int c = threadIdx.x;
    float a0 = 0.f, a1 = 0.f;
    #pragma unroll 2
    for (int k = 0; k < EMB; k++) {
        float rv = row[k];
        a0 = fmaf(rv, w_in[(size_t)k * HID + c],       a0);
        a1 = fmaf(rv, w_in[(size_t)k * HID + c + 256], a1);
    }
    g_UV[(size_t)r * HID + c]       = a0;
    g_UV[(size_t)r * HID + c + 256] = a1;
}

// ---------------------------------------------------------------------------
// Combine: H0 = silu(UV[h] + UV[128+b] + b_in), written as bf16 hi/lo
// ---------------------------------------------------------------------------
__global__ void __launch_bounds__(256)
combine_kernel(const float* __restrict__ b_in) {
    int idx4 = blockIdx.x * blockDim.x + threadIdx.x;
    int c4 = idx4 & (HID / 4 - 1);
    int r  = idx4 >> 7;
    int b = r >> 7, h = r & 127;

    float4 u = *reinterpret_cast<const float4*>(&g_UV[(size_t)h * HID + c4 * 4]);
    float4 v = *reinterpret_cast<const float4*>(&g_UV[(size_t)(NH + b) * HID + c4 * 4]);
    float4 bb = *reinterpret_cast<const float4*>(&b_in[c4 * 4]);
    float o[4];
    o[0] = silu_f(u.x + v.x + bb.x);
    o[1] = silu_f(u.y + v.y + bb.y);
    o[2] = silu_f(u.z + v.z + bb.z);
    o[3] = silu_f(u.w + v.w + bb.w);

    size_t base = (size_t)r * HID + c4 * 4;
    #pragma unroll
    for (int i = 0; i < 4; i += 2) {
        __nv_bfloat16 h0 = __float2bfloat16(o[i]);
        __nv_bfloat16 h1 = __float2bfloat16(o[i + 1]);
        __nv_bfloat162 hp, lp;
        hp.x = h0; hp.y = h1;
        lp.x = __float2bfloat16(o[i]     - __bfloat162float(h0));
        lp.y = __float2bfloat16(o[i + 1] - __bfloat162float(h1));
        *reinterpret_cast<__nv_bfloat162*>(&g_Ah[0][base + i]) = hp;
        *reinterpret_cast<__nv_bfloat162*>(&g_Al[0][base + i]) = lp;
    }
}

// ---------------------------------------------------------------------------
// Output projection from hi/lo activations (one warp per row)
// ---------------------------------------------------------------------------
__global__ void out_proj(const __nv_bfloat16* __restrict__ Hh,
                         const __nv_bfloat16* __restrict__ Hl,
                         const float* __restrict__ w_out,
                         const float* __restrict__ b_out) {
    int warp = (blockIdx.x * blockDim.x + threadIdx.x) >> 5;
    int lane = threadIdx.x & 31;
    if (warp >= ROWS) return;
    const __nv_bfloat16* hh = Hh + (size_t)warp * HID;
    const __nv_bfloat16* ll = Hl + (size_t)warp * HID;
    float a0 = 0.f, a1 = 0.f;
    #pragma unroll
    for (int k = lane; k < HID; k += 32) {
        float hv = __bfloat162float(hh[k]) + __bfloat162float(ll[k]);
        float2 w = *reinterpret_cast<const float2*>(w_out + 2 * k);
        a0 = fmaf(hv, w.x, a0);
        a1 = fmaf(hv, w.y, a1);
    }
    #pragma unroll
    for (int o = 16; o; o >>= 1) {
        a0 += __shfl_xor_sync(0xffffffffu, a0, o);
        a1 += __shfl_xor_sync(0xffffffffu, a1, o);
    }
    if (lane == 0) {
        g_coef[2 * warp + 0] = a0 + b_out[0];
        g_coef[2 * warp + 1] = a1 + b_out[1];
    }
}

// ---------------------------------------------------------------------------
// Fourier synthesis: one sincos + angle-addition recurrence over 128 harmonics
// ---------------------------------------------------------------------------
__global__ void __launch_bounds__(256)
synth_kernel(const float* __restrict__ target_x, float* __restrict__ out) {
    __shared__ float sc[NH], cc[NH];
    const int b = blockIdx.y;
    const int t = threadIdx.x;
    if (t < NH) {
        float2 v = *reinterpret_cast<const float2*>(&g_coef[(b * NH + t) * 2]);
        sc[t] = v.x;
        cc[t] = v.y;
    }
    __syncthreads();

    const int s = blockIdx.x * blockDim.x + t;
    float xv = target_x[b * SLEN + s];
    float theta = 6.283185307179586f * xv;
    float s1, c1;
    sincosf(theta, &s1, &c1);

    float ch = c1, sh = s1;
    float acc = 0.f;
    #pragma unroll 8
    for (int h = 0; h < NH; h++) {
        acc = fmaf(ch, cc[h], acc);
        acc = fmaf(sh, sc[h], acc);
        float nc = fmaf(ch, c1, -sh * s1);
        float ns = fmaf(sh, c1,  ch * s1);
        ch = nc;
        sh = ns;
    }
    out[b * SLEN + s] = acc;
}

// ---------------------------------------------------------------------------
// Launch sequence
// ---------------------------------------------------------------------------
extern "C" void kernel_launch(void* const* d_in, const int* in_sizes, int n_in,
                              void* d_out, int out_size) {
    const float* target_x = (const float*)d_in[0];
    const float* z        = (const float*)d_in[1];
    const float* emb      = (const float*)d_in[3];
    const float* w_in     = (const float*)d_in[4];
    const float* b_in     = (const float*)d_in[5];
    const float* w_h      = (const float*)d_in[6];
    const float* b_h      = (const float*)d_in[7];
    const float* w_out    = (const float*)d_in[8];
    const float* b_out    = (const float*)d_in[9];
    float* out = (float*)d_out;

    __nv_bfloat16 *Ah, *Al, *Wh, *Wl;
    cudaGetSymbolAddress((void**)&Ah, g_Ah);
    cudaGetSymbolAddress((void**)&Al, g_Al);
    cudaGetSymbolAddress((void**)&Wh, g_Wh);
    cudaGetSymbolAddress((void**)&Wl, g_Wl);
    __nv_bfloat16* Ah1 = Ah + (size_t)ROWS * HID;
    __nv_bfloat16* Al1 = Al + (size_t)ROWS * HID;

    // Idempotent; called every time (no static guards allowed).
    cudaFuncSetAttribute(gemm_mma, cudaFuncAttributeMaxDynamicSharedMemorySize, SM_TOTAL);

    // 1) weight split/transpose + input projection
    wprep<<<(3 * HID * HID + 255) / 256, 256>>>(w_h);
    in_gemm<<<URows, 256>>>(z, emb, w_in);

    // 2) combine -> hi/lo activations (buf 0)
    combine_kernel<<<(ROWS * HID / 4) / 256, 256>>>(b_in);

    // 3) hidden layers on tensor cores (bf16x3 split, fp32 accumulate)
    dim3 gg(HID / TILE_N, ROWS / TILE_M);   // (4, 64)
    gemm_mma<<<gg, 256, SM_TOTAL>>>(Ah,  Al,  Wh,                 Wl,                 b_h,           Ah1, Al1);
    gemm_mma<<<gg, 256, SM_TOTAL>>>(Ah1, Al1, Wh + HID * HID,     Wl + HID * HID,     b_h + HID,     Ah,  Al);
    gemm_mma<<<gg, 256, SM_TOTAL>>>(Ah,  Al,  Wh + 2 * HID * HID, Wl + 2 * HID * HID, b_h + 2 * HID, Ah1, Al1);

    // 4) output projection -> coefficients
    out_proj<<<(ROWS * 32) / 256, 256>>>(Ah1, Al1, w_out, b_out);

    // 5) Fourier synthesis
    dim3 sg(SLEN / 256, BSZ);
    synth_kernel<<<sg, 256>>>(target_x, out);
}